// round 1
// baseline (speedup 1.0000x reference)
#include <cuda_runtime.h>
#include <math.h>

// WaveNet collapsed to the last-sample recurrence.
//
// Shapes (from reference):
//   x        [8, 6, 8192]
//   start_w  [32, 6, 1]
//   filter_w [40, 32, 32, 2]   (only k=0 tap reaches the last sample)
//   gate_w   [40, 32, 32, 2]
//   res_w    [40, 32, 32, 1]
//   skip_w   [40, 256, 32, 1]
//   end1_w   [256, 256, 1], end1_b [256]
//   end2_w   [1, 256, 1],   end2_b [1]
// out: [8, 1] float32
//
// Math: the dilated conv (K=2, symmetric pad d) at the final output index
// uses only the k=0 tap (k=1 lands in the trailing zero pad). Hence the
// last sample of each layer depends only on the last sample of the previous
// layer:
//   u = tanh(F0 @ x) * sigmoid(G0 @ x)
//   skip_acc += S @ u
//   x = R @ u + u
// Then out = end2 @ relu(end1 @ relu(skip_acc) + b1) + b2.

#define NL 40
#define RC 32
#define SC 256
#define CIN 6
#define T_IN 8192

__global__ __launch_bounds__(256, 1)
void wavenet_last_kernel(const float* __restrict__ x,
                         const float* __restrict__ start_w,
                         const float* __restrict__ filter_w,
                         const float* __restrict__ gate_w,
                         const float* __restrict__ res_w,
                         const float* __restrict__ skip_w,
                         const float* __restrict__ end1_w,
                         const float* __restrict__ end1_b,
                         const float* __restrict__ end2_w,
                         const float* __restrict__ end2_b,
                         float* __restrict__ out)
{
    const int b    = blockIdx.x;       // batch index, grid = 8
    const int tid  = threadIdx.x;      // 0..255
    const int lane = tid & 31;
    const int warp = tid >> 5;

    __shared__ float xs[RC];           // current 32-dim state
    __shared__ float us[RC];           // gated activation u
    __shared__ float hs[SC];           // relu(skip_sum) for the head
    __shared__ float red[8];           // block reduction scratch

    // ---- start conv: x0[c] = sum_i start_w[c,i] * x[b,i,T-1] ----
    if (tid < RC) {
        float s = 0.f;
        #pragma unroll
        for (int i = 0; i < CIN; i++) {
            s += start_w[tid * CIN + i] * x[(b * CIN + i) * T_IN + (T_IN - 1)];
        }
        xs[tid] = s;
    }
    __syncthreads();

    float skip_acc = 0.f;              // thread tid owns skip channel tid

    for (int L = 0; L < NL; L++) {
        // --- warp 0: f/g GEMVs + gating ---
        if (warp == 0) {
            const float* Fw = filter_w + L * (RC * RC * 2) + lane * (RC * 2);
            const float* Gw = gate_w   + L * (RC * RC * 2) + lane * (RC * 2);
            float f0 = 0.f, f1 = 0.f, g0 = 0.f, g1 = 0.f;
            #pragma unroll
            for (int j = 0; j < RC; j += 2) {
                float xj0 = xs[j];
                float xj1 = xs[j + 1];
                f0 = fmaf(Fw[j * 2],       xj0, f0);
                f1 = fmaf(Fw[(j + 1) * 2], xj1, f1);
                g0 = fmaf(Gw[j * 2],       xj0, g0);
                g1 = fmaf(Gw[(j + 1) * 2], xj1, g1);
            }
            float f = f0 + f1;
            float g = g0 + g1;
            float t  = tanhf(f);
            float sg = 1.f / (1.f + expf(-g));
            us[lane] = t * sg;
        }
        __syncthreads();

        // --- all 256 threads: skip GEMV, one output channel each ---
        {
            const float* Sw = skip_w + L * (SC * RC) + tid * RC;
            float s0 = 0.f, s1 = 0.f, s2 = 0.f, s3 = 0.f;
            #pragma unroll
            for (int j = 0; j < RC; j += 4) {
                s0 = fmaf(Sw[j],     us[j],     s0);
                s1 = fmaf(Sw[j + 1], us[j + 1], s1);
                s2 = fmaf(Sw[j + 2], us[j + 2], s2);
                s3 = fmaf(Sw[j + 3], us[j + 3], s3);
            }
            skip_acc += (s0 + s1) + (s2 + s3);
        }

        // --- warp 1: residual GEMV + state update (overlaps with skip work) ---
        if (warp == 1) {
            const float* Rw = res_w + L * (RC * RC) + lane * RC;
            float r0 = 0.f, r1 = 0.f;
            #pragma unroll
            for (int j = 0; j < RC; j += 2) {
                r0 = fmaf(Rw[j],     us[j],     r0);
                r1 = fmaf(Rw[j + 1], us[j + 1], r1);
            }
            xs[lane] = r0 + r1 + us[lane];
        }
        __syncthreads();
    }

    // ---- head: relu(skip) -> end1 (256x256) + b1, relu -> end2 (1x256) + b2
    hs[tid] = fmaxf(skip_acc, 0.f);
    __syncthreads();

    float e = end1_b[tid];
    {
        const float* Ew = end1_w + tid * SC;
        float e0 = 0.f, e1 = 0.f, e2 = 0.f, e3 = 0.f;
        #pragma unroll 8
        for (int j = 0; j < SC; j += 4) {
            e0 = fmaf(Ew[j],     hs[j],     e0);
            e1 = fmaf(Ew[j + 1], hs[j + 1], e1);
            e2 = fmaf(Ew[j + 2], hs[j + 2], e2);
            e3 = fmaf(Ew[j + 3], hs[j + 3], e3);
        }
        e += (e0 + e1) + (e2 + e3);
    }
    e = fmaxf(e, 0.f);

    // out[b] = sum_c end2_w[c] * e[c] + end2_b[0]
    float o = end2_w[tid] * e;
    #pragma unroll
    for (int off = 16; off > 0; off >>= 1)
        o += __shfl_xor_sync(0xffffffffu, o, off);
    if (lane == 0) red[warp] = o;
    __syncthreads();
    if (tid == 0) {
        float tot = 0.f;
        #pragma unroll
        for (int w = 0; w < 8; w++) tot += red[w];
        out[b] = tot + end2_b[0];
    }
}

extern "C" void kernel_launch(void* const* d_in, const int* in_sizes, int n_in,
                              void* d_out, int out_size)
{
    const float* x        = (const float*)d_in[0];
    const float* start_w  = (const float*)d_in[1];
    const float* filter_w = (const float*)d_in[2];
    const float* gate_w   = (const float*)d_in[3];
    const float* res_w    = (const float*)d_in[4];
    const float* skip_w   = (const float*)d_in[5];
    const float* end1_w   = (const float*)d_in[6];
    const float* end1_b   = (const float*)d_in[7];
    const float* end2_w   = (const float*)d_in[8];
    const float* end2_b   = (const float*)d_in[9];
    float* out = (float*)d_out;

    wavenet_last_kernel<<<8, 256>>>(x, start_w, filter_w, gate_w, res_w, skip_w,
                                    end1_w, end1_b, end2_w, end2_b, out);
}

// round 2
// speedup vs baseline: 5.1612x; 5.1612x over previous
#include <cuda_runtime.h>
#include <math.h>

// WaveNet collapsed to the last-sample recurrence (see round-1 derivation):
// only the k=0 tap of each dilated conv reaches the final output index, so
// the whole network is a 32-dim recurrence per batch:
//   u_L = tanh(F_L x) * sigmoid(G_L x);  x = R_L u_L + u_L
//   skip_sum = sum_L S_L u_L ;  out = end2 @ relu(end1 @ relu(skip_sum)+b1)+b2
//
// Two launches:
//   1) pack kernel: k=0 extraction of F/G + R into bank-padded layout,
//      skip_w transposed to channel-major, start-conv precompute.
//      (Everything it writes is L2-resident for kernel 2.)
//   2) main kernel: grid=8 (batch), 256 thr. Warps 0-3 = recurrence from
//      smem; warps 4-7 = register-double-buffered smem producer. Skip GEMM
//      deferred to the end as a coalesced register-accumulator GEMM.

#define NL   40
#define RC   32
#define SC   256
#define CIN  6
#define T_IN 8192

// packed per-layer layout (floats): F rows @0 (32*33), G @1064, R @2128; stride 3200
#define LSTRIDE 3200
#define G_OFF   1064
#define R_OFF   2128

__device__ float g_fgr[NL * LSTRIDE];       // 512 KB
__device__ float g_skipT[SC * (NL * RC)];   // 1.31 MB, row-major [c][k], k = L*32+j
__device__ float g_xs0[8 * RC];             // start-conv states

// ---------------------------------------------------------------- pack kernel
__global__ void wn_pack(const float* __restrict__ x,
                        const float* __restrict__ start_w,
                        const float* __restrict__ filter_w,
                        const float* __restrict__ gate_w,
                        const float* __restrict__ res_w,
                        const float* __restrict__ skip_w)
{
    const int N1 = NL * 3 * RC * RC;   // 122880 F/G/R elements
    const int N2 = SC * NL * RC;       // 327680 skipT elements
    const int total = N1 + N2 + 8 * RC;

    for (int idx = blockIdx.x * blockDim.x + threadIdx.x; idx < total;
         idx += gridDim.x * blockDim.x) {
        if (idx < N1) {
            int L   = idx / (3 * RC * RC);
            int rem = idx % (3 * RC * RC);
            int w   = rem / (RC * RC);       // 0=F 1=G 2=R
            int i   = (rem % (RC * RC)) / RC;
            int j   = rem % RC;
            float v;
            if (w == 0)      v = filter_w[L * (RC * RC * 2) + i * (RC * 2) + j * 2];
            else if (w == 1) v = gate_w  [L * (RC * RC * 2) + i * (RC * 2) + j * 2];
            else             v = res_w   [L * (RC * RC)     + i * RC       + j];
            int off = (w == 0) ? 0 : (w == 1 ? G_OFF : R_OFF);
            g_fgr[L * LSTRIDE + off + i * 33 + j] = v;
        } else if (idx < N1 + N2) {
            int t = idx - N1;
            int c = t / (NL * RC);
            int k = t % (NL * RC);
            int L = k / RC, j = k % RC;
            g_skipT[c * (NL * RC) + k] = skip_w[L * (SC * RC) + c * RC + j];
        } else {
            int t = idx - N1 - N2;
            int b = t / RC, i = t % RC;
            float s = 0.f;
            #pragma unroll
            for (int ci = 0; ci < CIN; ci++)
                s += start_w[i * CIN + ci] * x[(b * CIN + ci) * T_IN + (T_IN - 1)];
            g_xs0[b * RC + i] = s;
        }
    }
}

// ---------------------------------------------------------------- main kernel
__global__ __launch_bounds__(256, 1)
void wn_main(const float* __restrict__ end1_w,
             const float* __restrict__ end1_b,
             const float* __restrict__ end2_w,
             const float* __restrict__ end2_b,
             float* __restrict__ out)
{
    const int b    = blockIdx.x;
    const int tid  = threadIdx.x;
    const int lane = tid & 31;
    const int warp = tid >> 5;

    __shared__ __align__(16) float ring[2][LSTRIDE];   // 25.6 KB
    __shared__ __align__(16) float us_all[NL * RC];    // 5.1 KB (flat k-major)
    __shared__ __align__(16) float xs[RC];
    __shared__ __align__(16) float hs[SC];
    __shared__ __align__(16) float ee[SC];
    __shared__ float red8[8];

    // -------- prologue: layer0 -> smem directly; layer1 -> producer regs
    float pf[25];
    if (tid >= 128) {                       // producer warps: prefetch layer 1
        const int pb = (tid - 128) * 25;    // 128*25 = 3200 exactly
        #pragma unroll
        for (int e = 0; e < 25; e++) pf[e] = g_fgr[LSTRIDE + pb + e];
    } else {                                // compute warps: copy layer 0
        const int pb = tid * 25;
        #pragma unroll
        for (int e = 0; e < 25; e++) ring[0][pb + e] = g_fgr[pb + e];
    }
    if (tid < RC) xs[tid] = g_xs0[b * RC + tid];
    __syncthreads();

    // -------- recurrence
    for (int L = 0; L < NL; L++) {
        const float* cur = ring[L & 1];

        if (warp < 4) {
            // phase 1: f/g GEMV. 4 threads per channel:
            //   r = tid&3 : (0,1)=tanh halves, (2,3)=sigmoid halves
            const int i  = tid >> 2;
            const int r  = tid & 3;
            const int h  = r & 1;
            const int fg = r >> 1;
            const float* wrow = cur + fg * G_OFF + i * 33 + h * 16;
            const float* xp   = xs + h * 16;
            float v0 = 0.f, v1 = 0.f;
            #pragma unroll
            for (int m = 0; m < 16; m += 2) {
                v0 = fmaf(wrow[m],     xp[m],     v0);
                v1 = fmaf(wrow[m + 1], xp[m + 1], v1);
            }
            float v = v0 + v1;
            v += __shfl_xor_sync(0xffffffffu, v, 1);   // combine halves
            float act;
            if (fg == 0) {      // tanh(v) = (e^{2v}-1)/(e^{2v}+1)
                float e2 = __expf(2.f * v);
                act = __fdividef(e2 - 1.f, e2 + 1.f);
            } else {            // sigmoid(v) = 1/(1+e^{-v})
                float e = __expf(-v);
                act = __fdividef(1.f, 1.f + e);
            }
            float other = __shfl_xor_sync(0xffffffffu, act, 2);
            if (r == 0) us_all[L * RC + i] = act * other;
        } else {
            // producer: store layer L+1 from regs
            if (L + 1 < NL) {
                const int pb = (tid - 128) * 25;
                float* dst = ring[(L + 1) & 1] + pb;
                #pragma unroll
                for (int e = 0; e < 25; e++) dst[e] = pf[e];
            }
        }
        __syncthreads();

        if (warp < 2) {
            // phase 2: residual GEMV + state update (2 threads per channel)
            const int i = tid >> 1;
            const int h = tid & 1;
            const float* rrow = cur + R_OFF + i * 33 + h * 16;
            const float* up   = us_all + L * RC + h * 16;
            float v0 = 0.f, v1 = 0.f;
            #pragma unroll
            for (int m = 0; m < 16; m += 2) {
                v0 = fmaf(rrow[m],     up[m],     v0);
                v1 = fmaf(rrow[m + 1], up[m + 1], v1);
            }
            float v = v0 + v1;
            v += __shfl_xor_sync(0xffffffffu, v, 1);
            if (h == 0) xs[i] = v + us_all[L * RC + i];
        } else if (tid >= 128) {
            // producer: issue loads for layer L+2
            if (L + 2 < NL) {
                const int pb = (tid - 128) * 25;
                const float* src = g_fgr + (L + 2) * LSTRIDE + pb;
                #pragma unroll
                for (int e = 0; e < 25; e++) pf[e] = src[e];
            }
        }
        __syncthreads();
    }

    // -------- deferred skip GEMM: skip[c] = sum_k S_T[c][k] * u[k], K=1280
    // warp w owns channels [32w, 32w+32); lane j covers k = 4*(j+32m)
    {
        float acc[32];
        #pragma unroll
        for (int c = 0; c < 32; c++) acc[c] = 0.f;
        #pragma unroll
        for (int m = 0; m < 10; m++) {
            float4 u4 = *reinterpret_cast<const float4*>(us_all + 4 * (lane + 32 * m));
            #pragma unroll
            for (int c = 0; c < 32; c++) {
                const float4 s4 = *reinterpret_cast<const float4*>(
                    g_skipT + (warp * 32 + c) * (NL * RC) + 4 * lane + 128 * m);
                acc[c] = fmaf(s4.x, u4.x, fmaf(s4.y, u4.y,
                         fmaf(s4.z, u4.z, fmaf(s4.w, u4.w, acc[c]))));
            }
        }
        float sk = 0.f;
        #pragma unroll
        for (int c = 0; c < 32; c++) {
            float v = acc[c];
            #pragma unroll
            for (int off = 16; off > 0; off >>= 1)
                v += __shfl_xor_sync(0xffffffffu, v, off);
            if (lane == c) sk = v;
        }
        hs[tid] = fmaxf(sk, 0.f);          // channel = 32*warp + lane = tid
    }
    __syncthreads();

    // -------- end1: e[c] = relu( sum_j E1[c][j] h[j] + b1[c] ), K=256
    {
        float acc[32];
        #pragma unroll
        for (int c = 0; c < 32; c++) acc[c] = 0.f;
        #pragma unroll
        for (int m = 0; m < 2; m++) {
            float4 h4 = *reinterpret_cast<const float4*>(hs + 4 * (lane + 32 * m));
            #pragma unroll
            for (int c = 0; c < 32; c++) {
                const float4 e4 = *reinterpret_cast<const float4*>(
                    end1_w + (warp * 32 + c) * SC + 4 * lane + 128 * m);
                acc[c] = fmaf(e4.x, h4.x, fmaf(e4.y, h4.y,
                         fmaf(e4.z, h4.z, fmaf(e4.w, h4.w, acc[c]))));
            }
        }
        float ev = 0.f;
        #pragma unroll
        for (int c = 0; c < 32; c++) {
            float v = acc[c];
            #pragma unroll
            for (int off = 16; off > 0; off >>= 1)
                v += __shfl_xor_sync(0xffffffffu, v, off);
            if (lane == c) ev = v;
        }
        ee[tid] = fmaxf(ev + end1_b[tid], 0.f);
    }
    __syncthreads();

    // -------- end2: scalar dot over 256
    {
        float o = end2_w[tid] * ee[tid];
        #pragma unroll
        for (int off = 16; off > 0; off >>= 1)
            o += __shfl_xor_sync(0xffffffffu, o, off);
        if (lane == 0) red8[warp] = o;
        __syncthreads();
        if (tid == 0) {
            float tot = 0.f;
            #pragma unroll
            for (int w = 0; w < 8; w++) tot += red8[w];
            out[b] = tot + end2_b[0];
        }
    }
}

extern "C" void kernel_launch(void* const* d_in, const int* in_sizes, int n_in,
                              void* d_out, int out_size)
{
    const float* x        = (const float*)d_in[0];
    const float* start_w  = (const float*)d_in[1];
    const float* filter_w = (const float*)d_in[2];
    const float* gate_w   = (const float*)d_in[3];
    const float* res_w    = (const float*)d_in[4];
    const float* skip_w   = (const float*)d_in[5];
    const float* end1_w   = (const float*)d_in[6];
    const float* end1_b   = (const float*)d_in[7];
    const float* end2_w   = (const float*)d_in[8];
    const float* end2_b   = (const float*)d_in[9];
    float* out = (float*)d_out;

    wn_pack<<<880, 512>>>(x, start_w, filter_w, gate_w, res_w, skip_w);
    wn_main<<<8, 256>>>(end1_w, end1_b, end2_w, end2_b, out);
}